// round 16
// baseline (speedup 1.0000x reference)
#include <cuda_runtime.h>
#include <cuda_bf16.h>
#include <cuda_fp16.h>
#include <mma.h>
#include <cstdint>

using namespace nvcuda;

#define N_NODES 100000
#define N_EDGES 3200000
#define N_GRAPHS 1000
#define HID 64
#define NL 4

#define SCAN_NBLK ((N_NODES + 1023) / 1024)   // 98
#define AST 72                                 // bf16 smem stride (elems)
#define DST 72                                 // fp32 strip stride (elems)

// ---------------- device scratch ----------------
__device__ float  g_h[N_NODES * HID];
__device__ __half g_af[N_NODES * HID];   // a = h@W1 (raw) in fp16 for cheap gather
__device__ float  g_c[N_NODES * HID];    // c = D3 + b3 + sumw*b1 - sumw*D2
__device__ int    g_deg[N_NODES];
__device__ float  g_sumw[N_NODES];
__device__ int    g_rowptr[N_NODES + 1];
__device__ int    g_cursor[N_NODES];
__device__ int2   g_edge[N_EDGES];       // packed (src, __float_as_int(ew))
__device__ int    g_idx64;
__device__ int    g_psum[SCAN_NBLK];
// pre-split weights: [l][mat][k][n], 64x64 bf16 row-major (ldm=64)
__device__ __nv_bfloat16 g_whi[NL * 3 * HID * HID];
__device__ __nv_bfloat16 g_wlo[NL * 3 * HID * HID];

__device__ __forceinline__ int idx_at(const void* p, long long pos) {
    return g_idx64 ? (int)((const long long*)p)[pos] : ((const int*)p)[pos];
}
__device__ __forceinline__ int clampi(int v, int hi) {
    return v < 0 ? 0 : (v >= hi ? hi - 1 : v);
}

// ---------------- fused init: dtype probe + zero + embed ----------------
__global__ void k_init(const void* __restrict__ ei,
                       const float* __restrict__ x,
                       const float* __restrict__ w,
                       const float* __restrict__ b) {
    int i = blockIdx.x * blockDim.x + threadIdx.x;
    if (i == 0) {
        const long long* p = (const long long*)ei;
        int ok64 = 1;
        for (int j = 0; j < 64; j++) {
            long long v = p[j];
            if (v < 0 || v >= N_NODES) { ok64 = 0; break; }
        }
        g_idx64 = ok64;
    }
    if (i < N_NODES) { g_deg[i] = 0; g_sumw[i] = 0.f; }
    if (i < N_NODES * HID) {
        int v = i >> 6, k = i & 63;
        const float* xr = x + v * 4;
        float acc = b[k];
#pragma unroll
        for (int j = 0; j < 4; j++) acc += xr[j] * w[j * HID + k];
        g_h[i] = acc;
    }
}

// ---------------- weight pre-split (once): fp32 -> bf16 hi/lo ----------------
__global__ void k_wsplit(const float* __restrict__ w1,
                         const float* __restrict__ w2,
                         const float* __restrict__ w3) {
    int i = blockIdx.x * blockDim.x + threadIdx.x;
    if (i < NL * 3 * HID * HID) {
        int slot = i >> 12;            // l*3 + mat
        int e    = i & 4095;
        int l    = slot / 3;
        int mat  = slot - l * 3;
        const float* W = (mat == 0) ? w1 : (mat == 1) ? w2 : w3;
        float v = W[l * HID * HID + e];
        __nv_bfloat16 hi = __float2bfloat16(v);
        g_whi[i] = hi;
        g_wlo[i] = __float2bfloat16(v - __bfloat162float(hi));
    }
}

// ---------------- CSR build ----------------
__global__ void k_hist(const void* __restrict__ ei) {
    int e = blockIdx.x * blockDim.x + threadIdx.x;
    if (e < N_EDGES) {
        int dst = clampi(idx_at(ei, (long long)N_EDGES + e), N_NODES);
        atomicAdd(&g_deg[dst], 1);
    }
}

__global__ void __launch_bounds__(1024) k_scan1() {
    __shared__ int sh[32];
    int i = blockIdx.x * 1024 + threadIdx.x;
    int v = (i < N_NODES) ? g_deg[i] : 0;
    for (int o = 16; o > 0; o >>= 1) v += __shfl_down_sync(0xffffffffu, v, o);
    if ((threadIdx.x & 31) == 0) sh[threadIdx.x >> 5] = v;
    __syncthreads();
    if (threadIdx.x < 32) {
        int s = sh[threadIdx.x];
        for (int o = 16; o > 0; o >>= 1) s += __shfl_down_sync(0xffffffffu, s, o);
        if (threadIdx.x == 0) g_psum[blockIdx.x] = s;
    }
}

__global__ void __launch_bounds__(1024) k_scan3() {
    __shared__ int sh[1024];
    __shared__ int swr[32];
    __shared__ int soff;
    int t = threadIdx.x;
    int po = (t < blockIdx.x) ? g_psum[t] : 0;
    for (int o = 16; o > 0; o >>= 1) po += __shfl_down_sync(0xffffffffu, po, o);
    if ((t & 31) == 0) swr[t >> 5] = po;
    __syncthreads();
    if (t < 32) {
        int s = swr[t];
        for (int o = 16; o > 0; o >>= 1) s += __shfl_down_sync(0xffffffffu, s, o);
        if (t == 0) soff = s;
    }
    int i = blockIdx.x * 1024 + t;
    int d = (i < N_NODES) ? g_deg[i] : 0;
    sh[t] = d;
    __syncthreads();
    for (int off = 1; off < 1024; off <<= 1) {
        int v = (t >= off) ? sh[t - off] : 0;
        __syncthreads();
        sh[t] += v;
        __syncthreads();
    }
    if (i < N_NODES) {
        int excl = soff + sh[t] - d;
        g_rowptr[i] = excl;
        g_cursor[i] = excl;
    }
    if (i == 0) g_rowptr[N_NODES] = N_EDGES;
}

// fill also accumulates sumw (measured cheaper than a separate pass in hist)
__global__ void k_fill(const void* __restrict__ ei, const float* __restrict__ ea) {
    int e = blockIdx.x * blockDim.x + threadIdx.x;
    if (e < N_EDGES) {
        int src = clampi(idx_at(ei, e), N_NODES);
        int dst = clampi(idx_at(ei, (long long)N_EDGES + e), N_NODES);
        float w = ea[e];
        atomicAdd(&g_sumw[dst], w);
        int pos = atomicAdd(&g_cursor[dst], 1);
        if (pos < N_EDGES)
            g_edge[pos] = make_int2(src, __float_as_int(w));
    }
}

// ---------------- WMMA split-bf16 fused 3-matrix GEMM ----------------
// Full 3-term split everywhere. k-outer loop: A fragments are TRANSIENT
// (reloaded per mat,k) to cut ~32 regs of live state; the aliasing hazard that
// broke R15 is fixed by keeping D2 in REGISTERS through mat2 — the A region is
// never overwritten until all A reads (mat2 inclusive) are done.
// 64 rows/CTA, 256 threads, 8 warps: warp w owns rows (w&3)*16, n-tiles (w>>2)*2..+1.
// D1 -> g_af (fp16). g_c = D3 + b3 + sumw*b1 - sumw*D2.
__global__ void __launch_bounds__(256) k_gemm_mma(
    int l, const float* __restrict__ B1all, const float* __restrict__ B3all)
{
    __shared__ __align__(16) char sm[36864];
    __nv_bfloat16* sAhi = (__nv_bfloat16*)(sm);
    __nv_bfloat16* sAlo = (__nv_bfloat16*)(sm + 9216);
    __nv_bfloat16* sWhi = (__nv_bfloat16*)(sm + 18432);
    __nv_bfloat16* sWlo = (__nv_bfloat16*)(sm + 27648);
    float* stripA = (float*)sm;             // aliases A region — used ONLY after mat2
    float* stripW = (float*)(sm + 18432);   // aliases W region — used between phases

    const float* B1 = B1all + l * HID;
    const float* B3 = B3all + l * HID;
    const uint32_t* WH = (const uint32_t*)(g_whi + (size_t)l * 3 * 4096);
    const uint32_t* WL = (const uint32_t*)(g_wlo + (size_t)l * 3 * 4096);

    const int t = threadIdx.x;
    const int w = t >> 5;
    const int mrow = (w & 3) * 16;
    const int ncol0 = (w >> 2) * 2;
    const int row0 = blockIdx.x * 64;

    // ---- A tile: load h, split hi/lo bf16 ----
    for (int i = t; i < 2048; i += 256) {        // 64 rows x 32 float2
        int r = i >> 5, kp = i & 31;
        int grow = row0 + r;
        float2 hv = make_float2(0.f, 0.f);
        if (grow < N_NODES) hv = ((const float2*)g_h)[grow * 32 + kp];
        __nv_bfloat16 h0 = __float2bfloat16(hv.x);
        __nv_bfloat16 h1 = __float2bfloat16(hv.y);
        sAhi[r * AST + kp * 2]     = h0;
        sAhi[r * AST + kp * 2 + 1] = h1;
        sAlo[r * AST + kp * 2]     = __float2bfloat16(hv.x - __bfloat162float(h0));
        sAlo[r * AST + kp * 2 + 1] = __float2bfloat16(hv.y - __bfloat162float(h1));
    }

    // helper: copy mat's pre-split weights into W region (callers sync around it)
#define W_COPY(MAT)                                                          \
    for (int i = t; i < 2048; i += 256) {                                    \
        int r = i >> 5, q = i & 31;                                          \
        uint32_t vh = WH[(MAT) * 2048 + i];                                  \
        uint32_t vl = WL[(MAT) * 2048 + i];                                  \
        *(uint32_t*)&sWhi[r * AST + q * 2] = vh;                             \
        *(uint32_t*)&sWlo[r * AST + q * 2] = vl;                             \
    }

    // helper: 3-term split MMA for this warp's two n-tiles into D0/D1
#define MAT_MMA(D0, D1)                                                      \
    wmma::fill_fragment(D0, 0.f);                                            \
    wmma::fill_fragment(D1, 0.f);                                            \
    _Pragma("unroll")                                                        \
    for (int k = 0; k < 4; k++) {                                            \
        wmma::fragment<wmma::matrix_a, 16, 16, 16, __nv_bfloat16, wmma::row_major> ah, al; \
        wmma::load_matrix_sync(ah, sAhi + mrow * AST + k * 16, AST);         \
        wmma::load_matrix_sync(al, sAlo + mrow * AST + k * 16, AST);         \
        {                                                                    \
            wmma::fragment<wmma::matrix_b, 16, 16, 16, __nv_bfloat16, wmma::row_major> bh, bl; \
            wmma::load_matrix_sync(bh, sWhi + (k * 16) * AST + ncol0 * 16, AST); \
            wmma::load_matrix_sync(bl, sWlo + (k * 16) * AST + ncol0 * 16, AST); \
            wmma::mma_sync(D0, ah, bh, D0);                                  \
            wmma::mma_sync(D0, al, bh, D0);                                  \
            wmma::mma_sync(D0, ah, bl, D0);                                  \
        }                                                                    \
        {                                                                    \
            wmma::fragment<wmma::matrix_b, 16, 16, 16, __nv_bfloat16, wmma::row_major> bh, bl; \
            wmma::load_matrix_sync(bh, sWhi + (k * 16) * AST + (ncol0 + 1) * 16, AST); \
            wmma::load_matrix_sync(bl, sWlo + (k * 16) * AST + (ncol0 + 1) * 16, AST); \
            wmma::mma_sync(D1, ah, bh, D1);                                  \
            wmma::mma_sync(D1, al, bh, D1);                                  \
            wmma::mma_sync(D1, ah, bl, D1);                                  \
        }                                                                    \
    }

    // ===== mat 0: D1a = h@W1 -> W-region strip -> g_af (fp16) =====
    __syncthreads();               // A tile stores visible
    W_COPY(0)
    __syncthreads();
    {
        wmma::fragment<wmma::accumulator, 16, 16, 16, float> d0, d1;
        MAT_MMA(d0, d1)
        __syncthreads();           // all warps done reading mat0 weights
        wmma::store_matrix_sync(stripW + mrow * DST + (ncol0 + 0) * 16, d0, DST,
                                wmma::mem_row_major);
        wmma::store_matrix_sync(stripW + mrow * DST + (ncol0 + 1) * 16, d1, DST,
                                wmma::mem_row_major);
    }
    __syncthreads();
    for (int i = t; i < 2048; i += 256) {        // 64 rows x 32 half2
        int r = i >> 5, q = i & 31;
        int row = row0 + r;
        if (row < N_NODES) {
            const float* s = stripW + r * DST + q * 2;
            ((__half2*)(g_af + (size_t)row * 64))[q] = __floats2half2_rn(s[0], s[1]);
        }
    }

    // ===== mat 1: D2 = h@W2 — kept in registers through mat 2 =====
    __syncthreads();               // strip reads (flush) done before W overwrite
    W_COPY(1)
    __syncthreads();
    wmma::fragment<wmma::accumulator, 16, 16, 16, float> e0, e1;
    MAT_MMA(e0, e1)

    // ===== mat 2: D3 = h@W3 =====
    __syncthreads();               // all warps done reading mat1 weights
    W_COPY(2)
    __syncthreads();
    wmma::fragment<wmma::accumulator, 16, 16, 16, float> f0, f1;
    MAT_MMA(f0, f1)

    // ---- all A and W reads complete: strips may now alias both regions ----
    __syncthreads();
    wmma::store_matrix_sync(stripA + mrow * DST + (ncol0 + 0) * 16, e0, DST,
                            wmma::mem_row_major);
    wmma::store_matrix_sync(stripA + mrow * DST + (ncol0 + 1) * 16, e1, DST,
                            wmma::mem_row_major);
    wmma::store_matrix_sync(stripW + mrow * DST + (ncol0 + 0) * 16, f0, DST,
                            wmma::mem_row_major);
    wmma::store_matrix_sync(stripW + mrow * DST + (ncol0 + 1) * 16, f1, DST,
                            wmma::mem_row_major);
    __syncthreads();

    // g_c = D3 + b3 + sumw*b1 - sumw*D2    (D2 in stripA, D3 in stripW)
    for (int i = t; i < 1024; i += 256) {        // 64 rows x 16 float4
        int r = i >> 4, q = i & 15;
        int row = row0 + r;
        if (row < N_NODES) {
            float sw = g_sumw[row];
            const float* s2 = stripA + r * DST + q * 4;
            const float* s3 = stripW + r * DST + q * 4;
            float4 b1v = ((const float4*)B1)[q];
            float4 b3v = ((const float4*)B3)[q];
            float4 cv;
            cv.x = s3[0] + b3v.x + sw * (b1v.x - s2[0]);
            cv.y = s3[1] + b3v.y + sw * (b1v.y - s2[1]);
            cv.z = s3[2] + b3v.z + sw * (b1v.z - s2[2]);
            cv.w = s3[3] + b3v.w + sw * (b1v.w - s2[3]);
            ((float4*)(g_c + (size_t)row * 64))[q] = cv;
        }
    }
#undef W_COPY
#undef MAT_MMA
}

// ---------------- edge aggregation (CSR, fp16 gather, int4 edge loads) ----------------
__global__ void __launch_bounds__(256) k_edge() {
    int v = blockIdx.x * 8 + (threadIdx.x >> 5);
    int kp = threadIdx.x & 31;
    if (v >= N_NODES) return;
    int lo = g_rowptr[v], hi = g_rowptr[v + 1];
    const __half2* __restrict__ A = (const __half2*)g_af;
    const int2* __restrict__ E = g_edge;
    float2 acc = ((const float2*)g_c)[v * 32 + kp];
    int e = lo;
    if ((e & 1) && e < hi) {
        int2 p = E[e];
        float2 av = __half22float2(A[p.x * 32 + kp]);
        float  wj = __int_as_float(p.y);
        acc.x += wj * av.x; acc.y += wj * av.y;
        e++;
    }
    const int4* __restrict__ E4 = (const int4*)E;
    for (; e + 7 < hi; e += 8) {
        int4 q[4];
        int b = e >> 1;
#pragma unroll
        for (int j = 0; j < 4; j++) q[j] = E4[b + j];
#pragma unroll
        for (int j = 0; j < 4; j++) {
            float2 a0 = __half22float2(A[q[j].x * 32 + kp]);
            float2 a1 = __half22float2(A[q[j].z * 32 + kp]);
            float  w0 = __int_as_float(q[j].y);
            float  w1 = __int_as_float(q[j].w);
            acc.x += w0 * a0.x; acc.y += w0 * a0.y;
            acc.x += w1 * a1.x; acc.y += w1 * a1.y;
        }
    }
    for (; e + 1 < hi; e += 2) {
        int4 q = E4[e >> 1];
        float2 a0 = __half22float2(A[q.x * 32 + kp]);
        float2 a1 = __half22float2(A[q.z * 32 + kp]);
        float  w0 = __int_as_float(q.y);
        float  w1 = __int_as_float(q.w);
        acc.x += w0 * a0.x; acc.y += w0 * a0.y;
        acc.x += w1 * a1.x; acc.y += w1 * a1.y;
    }
    if (e < hi) {
        int2 p = E[e];
        float2 av = __half22float2(A[p.x * 32 + kp]);
        float  wj = __int_as_float(p.y);
        acc.x += wj * av.x; acc.y += wj * av.y;
    }
    acc.x = fmaxf(acc.x, 0.f);
    acc.y = fmaxf(acc.y, 0.f);
    ((float2*)g_h)[v * 32 + kp] = acc;
}

// ---------------- pool + MLP head ----------------
__device__ __forceinline__ int lb_idx(const void* b, int val) {
    int lo = 0, hi = N_NODES;
    if (g_idx64) {
        const long long* p = (const long long*)b;
        long long v = (long long)val;
        while (lo < hi) { int m = (lo + hi) >> 1; if (p[m] < v) lo = m + 1; else hi = m; }
    } else {
        const int* p = (const int*)b;
        while (lo < hi) { int m = (lo + hi) >> 1; if (p[m] < val) lo = m + 1; else hi = m; }
    }
    return lo;
}

__global__ void __launch_bounds__(64) k_pool(
    const void* __restrict__ batch,
    const float* __restrict__ l1w, const float* __restrict__ l1b,
    const float* __restrict__ l2w, const float* __restrict__ l2b,
    float* __restrict__ out)
{
    int g = blockIdx.x;
    int k = threadIdx.x;
    __shared__ int s_lo, s_hi;
    __shared__ float gx[HID], hh[HID];
    if (k == 0) s_lo = lb_idx(batch, g);
    if (k == 1) s_hi = lb_idx(batch, g + 1);
    __syncthreads();
    int lo = s_lo, hi = s_hi;
    float s = 0.f;
    for (int v = lo; v < hi; v++) s += g_h[v * HID + k];
    float cnt = (float)(hi - lo);
    gx[k] = s / fmaxf(cnt, 1.f);
    __syncthreads();
    float acc = l1b[k];
#pragma unroll 8
    for (int i = 0; i < HID; i++) acc += gx[i] * l1w[i * HID + k];
    hh[k] = fmaxf(acc, 0.f);
    __syncthreads();
    if (k < 3) {
        float o = l2b[k];
#pragma unroll 8
        for (int i = 0; i < HID; i++) o += hh[i] * l2w[i * 3 + k];
        out[g * 3 + k] = o;
    }
}

// ---------------- launch ----------------
extern "C" void kernel_launch(void* const* d_in, const int* in_sizes, int n_in,
                              void* d_out, int out_size) {
    const float* x       = (const float*)d_in[0];
    const void*  eindex  = d_in[1];
    const float* eattr   = (const float*)d_in[2];
    const void*  batch   = d_in[3];
    const float* emb_w   = (const float*)d_in[4];
    const float* emb_b   = (const float*)d_in[5];
    const float* conv_w1 = (const float*)d_in[6];
    const float* conv_b1 = (const float*)d_in[7];
    const float* conv_w2 = (const float*)d_in[8];
    const float* conv_w3 = (const float*)d_in[9];
    const float* conv_b3 = (const float*)d_in[10];
    const float* lin1_w  = (const float*)d_in[11];
    const float* lin1_b  = (const float*)d_in[12];
    const float* lin2_w  = (const float*)d_in[13];
    const float* lin2_b  = (const float*)d_in[14];
    float*       out     = (float*)d_out;

    const int GEMM_GRID = (N_NODES + 63) / 64;   // 1563

    k_init<<<(N_NODES * HID + 255) / 256, 256>>>(eindex, x, emb_w, emb_b);
    k_hist<<<(N_EDGES + 255) / 256, 256>>>(eindex);
    k_wsplit<<<(NL * 3 * HID * HID + 255) / 256, 256>>>(conv_w1, conv_w2, conv_w3);
    k_scan1<<<SCAN_NBLK, 1024>>>();
    k_scan3<<<SCAN_NBLK, 1024>>>();
    k_fill<<<(N_EDGES + 255) / 256, 256>>>(eindex, eattr);   // sumw computed here

    for (int l = 0; l < NL; l++) {
        k_gemm_mma<<<GEMM_GRID, 256>>>(l, conv_b1, conv_b3);
        k_edge<<<(N_NODES + 7) / 8, 256>>>();
    }

    k_pool<<<N_GRAPHS, 64>>>(batch, lin1_w, lin1_b, lin2_w, lin2_b, out);
}

// round 17
// speedup vs baseline: 1.1574x; 1.1574x over previous
#include <cuda_runtime.h>
#include <cuda_bf16.h>
#include <cuda_fp16.h>
#include <mma.h>
#include <cstdint>

using namespace nvcuda;

#define N_NODES 100000
#define N_EDGES 3200000
#define N_GRAPHS 1000
#define HID 64
#define NL 4

#define SCAN_NBLK ((N_NODES + 1023) / 1024)   // 98
#define AST 72                                 // fp16 smem stride (elems)
#define DST 72                                 // fp32 strip stride (elems)

// ---------------- device scratch ----------------
__device__ float  g_h[N_NODES * HID];
__device__ __half g_af[N_NODES * HID];   // a = h@W1 (raw) in fp16 for cheap gather
__device__ float  g_c[N_NODES * HID];    // c = D3 + b3 + sumw*b1 - sumw*D2
__device__ int    g_deg[N_NODES];
__device__ float  g_sumw[N_NODES];
__device__ int    g_rowptr[N_NODES + 1];
__device__ int    g_cursor[N_NODES];
__device__ int2   g_edge[N_EDGES];       // packed (src, __float_as_int(ew))
__device__ int    g_idx64;
__device__ int    g_psum[SCAN_NBLK];
// pre-converted fp16 weights: [l][mat][k][n], 64x64 row-major
__device__ __half g_wh[NL * 3 * HID * HID];

__device__ __forceinline__ int idx_at(const void* p, long long pos) {
    return g_idx64 ? (int)((const long long*)p)[pos] : ((const int*)p)[pos];
}
__device__ __forceinline__ int clampi(int v, int hi) {
    return v < 0 ? 0 : (v >= hi ? hi - 1 : v);
}

// ---------------- fused init: dtype probe + zero + embed ----------------
__global__ void k_init(const void* __restrict__ ei,
                       const float* __restrict__ x,
                       const float* __restrict__ w,
                       const float* __restrict__ b) {
    int i = blockIdx.x * blockDim.x + threadIdx.x;
    if (i == 0) {
        const long long* p = (const long long*)ei;
        int ok64 = 1;
        for (int j = 0; j < 64; j++) {
            long long v = p[j];
            if (v < 0 || v >= N_NODES) { ok64 = 0; break; }
        }
        g_idx64 = ok64;
    }
    if (i < N_NODES) { g_deg[i] = 0; g_sumw[i] = 0.f; }
    if (i < N_NODES * HID) {
        int v = i >> 6, k = i & 63;
        const float* xr = x + v * 4;
        float acc = b[k];
#pragma unroll
        for (int j = 0; j < 4; j++) acc += xr[j] * w[j * HID + k];
        g_h[i] = acc;
    }
}

// ---------------- weight pre-convert (once): fp32 -> fp16 ----------------
__global__ void k_wconv(const float* __restrict__ w1,
                        const float* __restrict__ w2,
                        const float* __restrict__ w3) {
    int i = blockIdx.x * blockDim.x + threadIdx.x;
    if (i < NL * 3 * HID * HID) {
        int slot = i >> 12;            // l*3 + mat
        int e    = i & 4095;
        int l    = slot / 3;
        int mat  = slot - l * 3;
        const float* W = (mat == 0) ? w1 : (mat == 1) ? w2 : w3;
        g_wh[i] = __float2half_rn(W[l * HID * HID + e]);
    }
}

// ---------------- CSR build ----------------
__global__ void k_hist(const void* __restrict__ ei) {
    int e = blockIdx.x * blockDim.x + threadIdx.x;
    if (e < N_EDGES) {
        int dst = clampi(idx_at(ei, (long long)N_EDGES + e), N_NODES);
        atomicAdd(&g_deg[dst], 1);
    }
}

__global__ void __launch_bounds__(1024) k_scan1() {
    __shared__ int sh[32];
    int i = blockIdx.x * 1024 + threadIdx.x;
    int v = (i < N_NODES) ? g_deg[i] : 0;
    for (int o = 16; o > 0; o >>= 1) v += __shfl_down_sync(0xffffffffu, v, o);
    if ((threadIdx.x & 31) == 0) sh[threadIdx.x >> 5] = v;
    __syncthreads();
    if (threadIdx.x < 32) {
        int s = sh[threadIdx.x];
        for (int o = 16; o > 0; o >>= 1) s += __shfl_down_sync(0xffffffffu, s, o);
        if (threadIdx.x == 0) g_psum[blockIdx.x] = s;
    }
}

__global__ void __launch_bounds__(1024) k_scan3() {
    __shared__ int sh[1024];
    __shared__ int swr[32];
    __shared__ int soff;
    int t = threadIdx.x;
    int po = (t < blockIdx.x) ? g_psum[t] : 0;
    for (int o = 16; o > 0; o >>= 1) po += __shfl_down_sync(0xffffffffu, po, o);
    if ((t & 31) == 0) swr[t >> 5] = po;
    __syncthreads();
    if (t < 32) {
        int s = swr[t];
        for (int o = 16; o > 0; o >>= 1) s += __shfl_down_sync(0xffffffffu, s, o);
        if (t == 0) soff = s;
    }
    int i = blockIdx.x * 1024 + t;
    int d = (i < N_NODES) ? g_deg[i] : 0;
    sh[t] = d;
    __syncthreads();
    for (int off = 1; off < 1024; off <<= 1) {
        int v = (t >= off) ? sh[t - off] : 0;
        __syncthreads();
        sh[t] += v;
        __syncthreads();
    }
    if (i < N_NODES) {
        int excl = soff + sh[t] - d;
        g_rowptr[i] = excl;
        g_cursor[i] = excl;
    }
    if (i == 0) g_rowptr[N_NODES] = N_EDGES;
}

// fill also accumulates sumw (measured cheaper than a separate pass in hist)
__global__ void k_fill(const void* __restrict__ ei, const float* __restrict__ ea) {
    int e = blockIdx.x * blockDim.x + threadIdx.x;
    if (e < N_EDGES) {
        int src = clampi(idx_at(ei, e), N_NODES);
        int dst = clampi(idx_at(ei, (long long)N_EDGES + e), N_NODES);
        float w = ea[e];
        atomicAdd(&g_sumw[dst], w);
        int pos = atomicAdd(&g_cursor[dst], 1);
        if (pos < N_EDGES)
            g_edge[pos] = make_int2(src, __float_as_int(w));
    }
}

// ---------------- WMMA fp16 fused 3-matrix GEMM ----------------
// Single fp16 term per matrix (eps 2^-11 — same as the measured tf32 run at
// rel_err 2.3e-4), fp32 accumulators. 1/3 the MMAs and ~40% the LDSM of the
// split-bf16 scheme; no per-element fragment conversion (the tf32 failure).
// 64 rows/CTA, 256 threads, 8 warps: warp w owns rows (w&3)*16, n-tiles (w>>2)*2..+1.
// Persistent A fragments (4, fp16 = 16 regs). D1 -> g_af (fp16).
// g_c = D3 + b3 + sumw*b1 - sumw*D2.
__global__ void __launch_bounds__(256) k_gemm_mma(
    int l, const float* __restrict__ B1all, const float* __restrict__ B3all)
{
    __shared__ __align__(16) char sm[36864];
    __half* sA = (__half*)(sm);             // 64 x AST fp16 = 9216B
    __half* sW = (__half*)(sm + 9216);      // 64 x AST fp16 = 9216B
    float* strip1 = (float*)(sm + 18432);   // 64 x DST fp32 = 18432B (dedicated)
    float* strip2 = (float*)(sm);           // aliases A+W ONLY after all reads done

    const float* B1 = B1all + l * HID;
    const float* B3 = B3all + l * HID;
    const uint32_t* WH = (const uint32_t*)(g_wh + (size_t)l * 3 * 4096);

    const int t = threadIdx.x;
    const int w = t >> 5;
    const int mrow = (w & 3) * 16;
    const int ncol0 = (w >> 2) * 2;
    const int row0 = blockIdx.x * 64;

    // ---- A tile: load h, convert fp16 ----
    for (int i = t; i < 2048; i += 256) {        // 64 rows x 32 float2
        int r = i >> 5, kp = i & 31;
        int grow = row0 + r;
        float2 hv = make_float2(0.f, 0.f);
        if (grow < N_NODES) hv = ((const float2*)g_h)[grow * 32 + kp];
        *(__half2*)&sA[r * AST + kp * 2] = __floats2half2_rn(hv.x, hv.y);
    }
    // W copy for mat0 can overlap (disjoint smem region)
    for (int i = t; i < 2048; i += 256) {        // 64 k-rows x 32 fp16-pairs
        int r = i >> 5, q = i & 31;
        *(uint32_t*)&sW[r * AST + q * 2] = WH[i];
    }
    __syncthreads();

    wmma::fragment<wmma::matrix_a, 16, 16, 16, __half, wmma::row_major> af[4];
#pragma unroll
    for (int k = 0; k < 4; k++)
        wmma::load_matrix_sync(af[k], sA + mrow * AST + k * 16, AST);

#define MAT_MMA(D0, D1)                                                      \
    wmma::fill_fragment(D0, 0.f);                                            \
    wmma::fill_fragment(D1, 0.f);                                            \
    _Pragma("unroll")                                                        \
    for (int k = 0; k < 4; k++) {                                            \
        wmma::fragment<wmma::matrix_b, 16, 16, 16, __half, wmma::row_major> b0, b1; \
        wmma::load_matrix_sync(b0, sW + (k * 16) * AST + ncol0 * 16, AST);   \
        wmma::mma_sync(D0, af[k], b0, D0);                                   \
        wmma::load_matrix_sync(b1, sW + (k * 16) * AST + (ncol0 + 1) * 16, AST); \
        wmma::mma_sync(D1, af[k], b1, D1);                                   \
    }

    // ===== mat 0: D1 = h@W1 -> strip1 -> g_af (fp16) =====
    {
        wmma::fragment<wmma::accumulator, 16, 16, 16, float> d0, d1;
        MAT_MMA(d0, d1)
        wmma::store_matrix_sync(strip1 + mrow * DST + (ncol0 + 0) * 16, d0, DST,
                                wmma::mem_row_major);
        wmma::store_matrix_sync(strip1 + mrow * DST + (ncol0 + 1) * 16, d1, DST,
                                wmma::mem_row_major);
    }
    __syncthreads();   // mat0 MMA (sW reads) + strip1 stores complete

    // flush D1 -> g_af (reads strip1) while copying mat1 weights (writes sW): disjoint
    for (int i = t; i < 2048; i += 256) {        // 64 rows x 32 half2
        int r = i >> 5, q = i & 31;
        int row = row0 + r;
        if (row < N_NODES) {
            const float* s = strip1 + r * DST + q * 2;
            ((__half2*)(g_af + (size_t)row * 64))[q] = __floats2half2_rn(s[0], s[1]);
        }
    }
    for (int i = t; i < 2048; i += 256) {
        int r = i >> 5, q = i & 31;
        *(uint32_t*)&sW[r * AST + q * 2] = WH[2048 + i];
    }
    __syncthreads();   // flush reads done; mat1 weights in place

    // ===== mat 1: D2 = h@W2 -> strip1 =====
    {
        wmma::fragment<wmma::accumulator, 16, 16, 16, float> e0, e1;
        MAT_MMA(e0, e1)
        wmma::store_matrix_sync(strip1 + mrow * DST + (ncol0 + 0) * 16, e0, DST,
                                wmma::mem_row_major);
        wmma::store_matrix_sync(strip1 + mrow * DST + (ncol0 + 1) * 16, e1, DST,
                                wmma::mem_row_major);
    }
    __syncthreads();   // mat1 MMA reads of sW done

    // copy mat2 weights
    for (int i = t; i < 2048; i += 256) {
        int r = i >> 5, q = i & 31;
        *(uint32_t*)&sW[r * AST + q * 2] = WH[4096 + i];
    }
    __syncthreads();

    // ===== mat 2: D3 = h@W3 =====
    wmma::fragment<wmma::accumulator, 16, 16, 16, float> f0, f1;
    MAT_MMA(f0, f1)
    __syncthreads();   // ALL reads of sA/sW complete -> strip2 may alias them
    wmma::store_matrix_sync(strip2 + mrow * DST + (ncol0 + 0) * 16, f0, DST,
                            wmma::mem_row_major);
    wmma::store_matrix_sync(strip2 + mrow * DST + (ncol0 + 1) * 16, f1, DST,
                            wmma::mem_row_major);
    __syncthreads();

    // g_c = D3 + b3 + sumw*b1 - sumw*D2    (D2 in strip1, D3 in strip2)
    for (int i = t; i < 1024; i += 256) {        // 64 rows x 16 float4
        int r = i >> 4, q = i & 15;
        int row = row0 + r;
        if (row < N_NODES) {
            float sw = g_sumw[row];
            const float* s2 = strip1 + r * DST + q * 4;
            const float* s3 = strip2 + r * DST + q * 4;
            float4 b1v = ((const float4*)B1)[q];
            float4 b3v = ((const float4*)B3)[q];
            float4 cv;
            cv.x = s3[0] + b3v.x + sw * (b1v.x - s2[0]);
            cv.y = s3[1] + b3v.y + sw * (b1v.y - s2[1]);
            cv.z = s3[2] + b3v.z + sw * (b1v.z - s2[2]);
            cv.w = s3[3] + b3v.w + sw * (b1v.w - s2[3]);
            ((float4*)(g_c + (size_t)row * 64))[q] = cv;
        }
    }
#undef MAT_MMA
}

// ---------------- edge aggregation (CSR, fp16 gather, int4 edge loads) ----------------
__global__ void __launch_bounds__(256) k_edge() {
    int v = blockIdx.x * 8 + (threadIdx.x >> 5);
    int kp = threadIdx.x & 31;
    if (v >= N_NODES) return;
    int lo = g_rowptr[v], hi = g_rowptr[v + 1];
    const __half2* __restrict__ A = (const __half2*)g_af;
    const int2* __restrict__ E = g_edge;
    float2 acc = ((const float2*)g_c)[v * 32 + kp];
    int e = lo;
    if ((e & 1) && e < hi) {
        int2 p = E[e];
        float2 av = __half22float2(A[p.x * 32 + kp]);
        float  wj = __int_as_float(p.y);
        acc.x += wj * av.x; acc.y += wj * av.y;
        e++;
    }
    const int4* __restrict__ E4 = (const int4*)E;
    for (; e + 7 < hi; e += 8) {
        int4 q[4];
        int b = e >> 1;
#pragma unroll
        for (int j = 0; j < 4; j++) q[j] = E4[b + j];
#pragma unroll
        for (int j = 0; j < 4; j++) {
            float2 a0 = __half22float2(A[q[j].x * 32 + kp]);
            float2 a1 = __half22float2(A[q[j].z * 32 + kp]);
            float  w0 = __int_as_float(q[j].y);
            float  w1 = __int_as_float(q[j].w);
            acc.x += w0 * a0.x; acc.y += w0 * a0.y;
            acc.x += w1 * a1.x; acc.y += w1 * a1.y;
        }
    }
    for (; e + 1 < hi; e += 2) {
        int4 q = E4[e >> 1];
        float2 a0 = __half22float2(A[q.x * 32 + kp]);
        float2 a1 = __half22float2(A[q.z * 32 + kp]);
        float  w0 = __int_as_float(q.y);
        float  w1 = __int_as_float(q.w);
        acc.x += w0 * a0.x; acc.y += w0 * a0.y;
        acc.x += w1 * a1.x; acc.y += w1 * a1.y;
    }
    if (e < hi) {
        int2 p = E[e];
        float2 av = __half22float2(A[p.x * 32 + kp]);
        float  wj = __int_as_float(p.y);
        acc.x += wj * av.x; acc.y += wj * av.y;
    }
    acc.x = fmaxf(acc.x, 0.f);
    acc.y = fmaxf(acc.y, 0.f);
    ((float2*)g_h)[v * 32 + kp] = acc;
}

// ---------------- pool + MLP head ----------------
__device__ __forceinline__ int lb_idx(const void* b, int val) {
    int lo = 0, hi = N_NODES;
    if (g_idx64) {
        const long long* p = (const long long*)b;
        long long v = (long long)val;
        while (lo < hi) { int m = (lo + hi) >> 1; if (p[m] < v) lo = m + 1; else hi = m; }
    } else {
        const int* p = (const int*)b;
        while (lo < hi) { int m = (lo + hi) >> 1; if (p[m] < val) lo = m + 1; else hi = m; }
    }
    return lo;
}

__global__ void __launch_bounds__(64) k_pool(
    const void* __restrict__ batch,
    const float* __restrict__ l1w, const float* __restrict__ l1b,
    const float* __restrict__ l2w, const float* __restrict__ l2b,
    float* __restrict__ out)
{
    int g = blockIdx.x;
    int k = threadIdx.x;
    __shared__ int s_lo, s_hi;
    __shared__ float gx[HID], hh[HID];
    if (k == 0) s_lo = lb_idx(batch, g);
    if (k == 1) s_hi = lb_idx(batch, g + 1);
    __syncthreads();
    int lo = s_lo, hi = s_hi;
    float s = 0.f;
    for (int v = lo; v < hi; v++) s += g_h[v * HID + k];
    float cnt = (float)(hi - lo);
    gx[k] = s / fmaxf(cnt, 1.f);
    __syncthreads();
    float acc = l1b[k];
#pragma unroll 8
    for (int i = 0; i < HID; i++) acc += gx[i] * l1w[i * HID + k];
    hh[k] = fmaxf(acc, 0.f);
    __syncthreads();
    if (k < 3) {
        float o = l2b[k];
#pragma unroll 8
        for (int i = 0; i < HID; i++) o += hh[i] * l2w[i * 3 + k];
        out[g * 3 + k] = o;
    }
}

// ---------------- launch ----------------
extern "C" void kernel_launch(void* const* d_in, const int* in_sizes, int n_in,
                              void* d_out, int out_size) {
    const float* x       = (const float*)d_in[0];
    const void*  eindex  = d_in[1];
    const float* eattr   = (const float*)d_in[2];
    const void*  batch   = d_in[3];
    const float* emb_w   = (const float*)d_in[4];
    const float* emb_b   = (const float*)d_in[5];
    const float* conv_w1 = (const float*)d_in[6];
    const float* conv_b1 = (const float*)d_in[7];
    const float* conv_w2 = (const float*)d_in[8];
    const float* conv_w3 = (const float*)d_in[9];
    const float* conv_b3 = (const float*)d_in[10];
    const float* lin1_w  = (const float*)d_in[11];
    const float* lin1_b  = (const float*)d_in[12];
    const float* lin2_w  = (const float*)d_in[13];
    const float* lin2_b  = (const float*)d_in[14];
    float*       out     = (float*)d_out;

    const int GEMM_GRID = (N_NODES + 63) / 64;   // 1563

    k_init<<<(N_NODES * HID + 255) / 256, 256>>>(eindex, x, emb_w, emb_b);
    k_hist<<<(N_EDGES + 255) / 256, 256>>>(eindex);
    k_wconv<<<(NL * 3 * HID * HID + 255) / 256, 256>>>(conv_w1, conv_w2, conv_w3);
    k_scan1<<<SCAN_NBLK, 1024>>>();
    k_scan3<<<SCAN_NBLK, 1024>>>();
    k_fill<<<(N_EDGES + 255) / 256, 256>>>(eindex, eattr);   // sumw computed here

    for (int l = 0; l < NL; l++) {
        k_gemm_mma<<<GEMM_GRID, 256>>>(l, conv_b1, conv_b3);
        k_edge<<<(N_NODES + 7) / 8, 256>>>();
    }

    k_pool<<<N_GRAPHS, 64>>>(batch, lin1_w, lin1_b, lin2_w, lin2_b, out);
}